// round 16
// baseline (speedup 1.0000x reference)
#include <cuda_runtime.h>

// SpectralConv2d: B=16, C_IN=C_OUT=64, H=W=256, M=16
//  kAB: per (b,c), h-first pruned DFT, QUARTET symmetry {h,256-h,128-h,128+h},
//       registers-only x streaming (direct LDG, compile-time offsets, prefetch
//       distance 1 chunk, NO smem staging / NO mainloop barriers);
//       phase-aliased smem (p1: 8.8KB tables | p2: P+E2) -> 3 CTAs/SM.
//  kM : per-(m,q) complex channel mix [16x64]*[64x64].
//  kCD: parity-shared G build (h, h+128) + 2-column symmetric inverse-w GEMM.

#define NBC   (16*64)       // 1024

typedef unsigned long long u64;

__device__ float2 g_X2[NBC * 32 * 16];     // [bc][m][q]
__device__ float2 g_Y [NBC * 32 * 16];     // [bd][m][q]

__device__ __forceinline__ u64 pack2(float lo, float hi) {
    u64 r; asm("mov.b64 %0, {%1,%2};" : "=l"(r) : "f"(lo), "f"(hi)); return r;
}
__device__ __forceinline__ float2 unpack2(u64 v) {
    float lo, hi; asm("mov.b64 {%0,%1}, %2;" : "=f"(lo), "=f"(hi) : "l"(v));
    return make_float2(lo, hi);
}
__device__ __forceinline__ u64 fma2(u64 a, u64 b, u64 c) {
    u64 d; asm("fma.rn.f32x2 %0, %1, %2, %3;" : "=l"(d) : "l"(a), "l"(b), "l"(c)); return d;
}
__device__ __forceinline__ u64 add2(u64 a, u64 b) {
    u64 d; asm("add.rn.f32x2 %0, %1, %2;" : "=l"(d) : "l"(a), "l"(b)); return d;
}

// ================= Fused stage A+B (quartet, registers-only streaming) =========
// phase 1 (bytes): twE ulonglong2[65*4] @0 (4160) | twO @4160 (4160) |
//                  tw16 u64[65] @8320 (520)
// phase 2: P u64[17*257] @0 (34952->pad 34960) | E2 ulonglong2[129*16] @34960 (33024)
// smem = 67984 -> 3 CTAs/SM
__global__ __launch_bounds__(256, 3) void kAB(const float* __restrict__ x) {
    extern __shared__ char sm[];
    ulonglong2* twE  = (ulonglong2*)sm;
    ulonglong2* twO  = (ulonglong2*)(sm + 4160);
    u64*        tw16 = (u64*)(sm + 8320);
    u64*        P    = (u64*)sm;                   // phase-2 alias
    ulonglong2* E2   = (ulonglong2*)(sm + 34960);  // phase-2 alias

    const int tid = threadIdx.x;
    const size_t bc = blockIdx.x;
    const float k = 1.0f / 256.0f;
    const float* xb_ = x + bc * 65536;

    // twiddle tables: h = 1..64 (h=64 scaled 0.5 -> degenerate quartet correct)
    if (tid < 64) {
        int h = tid + 1;
        float sc = (h == 64) ? (0.5f * k) : k;
        float cb[17], sb[17];
        #pragma unroll
        for (int m = 0; m < 17; m++) {
            float s, c;
            sincospif((float)((m * h) & 255) * (1.0f / 128.0f), &s, &c);
            cb[m] = c * sc; sb[m] = s * sc;
        }
        #pragma unroll
        for (int j = 0; j < 4; j++) {
            ulonglong2 ve, vo;
            ve.x = pack2(cb[4 * j], cb[4 * j + 2]);
            ve.y = pack2(sb[4 * j], sb[4 * j + 2]);
            vo.x = pack2(cb[4 * j + 1], cb[4 * j + 3]);
            vo.y = pack2(sb[4 * j + 1], sb[4 * j + 3]);
            twE[h * 4 + j] = ve;
            twO[h * 4 + j] = vo;
        }
        tw16[h] = pack2(cb[16], sb[16]);
    }

    const int w = tid;
    const float* xw = xb_ + w;
    // special rows 0 and 128
    float x0 = __ldg(xw), x128 = __ldg(xw + 32768);

    // chunk loader: rows A=4c+1+i, B=256-(4c+1+i), C=128-(4c+1+i), D=128+(4c+1+i)
    // (c compile-time under full unroll -> LDG [reg+imm], zero address ALU)
    float cur[16], nxt[16];
    #pragma unroll
    for (int i = 0; i < 4; i++) {
        int h = 1 + i;
        cur[i]      = __ldg(xw + h * 256);
        cur[4 + i]  = __ldg(xw + (256 - h) * 256);
        cur[8 + i]  = __ldg(xw + (128 - h) * 256);
        cur[12 + i] = __ldg(xw + (128 + h) * 256);
    }
    __syncthreads();    // tables visible

    u64 accEA[4], accEB[4], accOA[4], accOB[4], acc16;
    {
        float ve = (x0 + x128) * k, vo = (x0 - x128) * k;
        u64 pe = pack2(ve, ve), po = pack2(vo, vo);
        #pragma unroll
        for (int j = 0; j < 4; j++) {
            accEA[j] = pe; accEB[j] = 0ull;
            accOA[j] = po; accOB[j] = 0ull;
        }
        acc16 = pack2(ve, 0.0f);
    }

    #pragma unroll
    for (int c = 0; c < 16; c++) {
        if (c < 15) {
            #pragma unroll
            for (int i = 0; i < 4; i++) {
                int h = 4 * (c + 1) + 1 + i;
                nxt[i]      = __ldg(xw + h * 256);
                nxt[4 + i]  = __ldg(xw + (256 - h) * 256);
                nxt[8 + i]  = __ldg(xw + (128 - h) * 256);
                nxt[12 + i] = __ldg(xw + (128 + h) * 256);
            }
        }
        const int hb = 4 * c + 1;
        #pragma unroll
        for (int i = 0; i < 4; i++) {
            float xa = cur[i], xv = cur[4 + i], xc = cur[8 + i], xd = cur[12 + i];
            float s_ = xa + xv, d_ = xa - xv;
            float s2 = xc + xd, d2 = xc - xd;
            float se = s_ + s2, so = s_ - s2;
            float de = d_ - d2, dO = d_ + d2;
            u64 sse = pack2(se, se), sso = pack2(so, so);
            u64 dde = pack2(de, de), ddo = pack2(dO, dO);
            const int ht = hb + i;
            const ulonglong2* tE = &twE[ht * 4];
            const ulonglong2* tO = &twO[ht * 4];
            #pragma unroll
            for (int j = 0; j < 4; j++) {
                ulonglong2 e = tE[j];
                ulonglong2 o = tO[j];
                accEA[j] = fma2(sse, e.x, accEA[j]);
                accEB[j] = fma2(dde, e.y, accEB[j]);
                accOA[j] = fma2(sso, o.x, accOA[j]);
                accOB[j] = fma2(ddo, o.y, accOB[j]);
            }
            acc16 = fma2(pack2(se, de), tw16[ht], acc16);
        }
        #pragma unroll
        for (int i = 0; i < 16; i++) cur[i] = nxt[i];
    }
    __syncthreads();   // table reads done before P/E2 overwrite

    // write P[m][w] = (A_m, B_m); build E2
    #pragma unroll
    for (int j = 0; j < 4; j++) {
        float2 aE = unpack2(accEA[j]), bE = unpack2(accEB[j]);
        float2 aO = unpack2(accOA[j]), bO = unpack2(accOB[j]);
        P[(4 * j) * 257 + w]     = pack2(aE.x, bE.x);
        P[(4 * j + 2) * 257 + w] = pack2(aE.y, bE.y);
        P[(4 * j + 1) * 257 + w] = pack2(aO.x, bO.x);
        P[(4 * j + 3) * 257 + w] = pack2(aO.y, bO.y);
    }
    P[16 * 257 + w] = acc16;
    for (int idx = tid; idx < 129 * 16; idx += 256) {
        int wp = idx >> 4, q = idx & 15;
        float s, c;
        sincospif((float)(q * wp) * (1.0f / 128.0f), &s, &c);
        ulonglong2 v; v.x = pack2(c, c); v.y = pack2(s, s);
        E2[idx] = v;
    }
    __syncthreads();

    // ---- phase 2: w-DFT on 17 m' rows (w-mirror), task = (m', q) ----
    for (int task = tid; task < 272; task += 256) {
        const int mp = task >> 4, q = task & 15;
        const u64* Pm = P + mp * 257;
        const u64 NEG1 = pack2(-1.0f, -1.0f);

        float sq = (q & 1) ? -1.0f : 1.0f;
        u64 acc1 = fma2(Pm[128], pack2(sq, sq), Pm[0]);   // (Cc, Dc)
        u64 acc2 = 0ull;                                   // (Cs, Ds)

        #pragma unroll 2
        for (int wp = 1; wp <= 127; wp++) {
            u64 Pa = Pm[wp];
            u64 Pb = Pm[256 - wp];
            u64 S = add2(Pa, Pb);
            u64 D = fma2(Pb, NEG1, Pa);
            ulonglong2 e = E2[wp * 16 + q];
            acc1 = fma2(S, e.x, acc1);
            acc2 = fma2(D, e.y, acc2);
        }
        float2 r1 = unpack2(acc1);   // (Cc, Dc)
        float2 r2 = unpack2(acc2);   // (Cs, Ds)
        float2* dst = g_X2 + bc * 512;
        if (mp <= 15) dst[mp * 16 + q]        = make_float2(r1.x - r2.y, -(r2.x + r1.y));
        if (mp >= 1)  dst[(32 - mp) * 16 + q] = make_float2(r1.x + r2.y, r1.y - r2.x);
    }
}

// ================= Channel mixing (unchanged) =================
__global__ __launch_bounds__(256) void kM(const float* __restrict__ w1,
                                          const float* __restrict__ w2) {
    extern __shared__ char smM[];
    float2* Xs = (float2*)smM;                       // [b*64+c]
    ulonglong2* Wpk = (ulonglong2*)(smM + 1024 * 8); // [c*64+d] = ((wr,wi),(-wi,wr))
    const int tid = threadIdx.x;
    const int m = blockIdx.x >> 4;
    const int q = blockIdx.x & 15;
    const float* wsrc = (m < 16) ? w1 : w2;
    const int t_w = (m < 16) ? m : (m - 16);

    for (int i = tid; i < 1024; i += 256) {
        int b = i >> 6, c = i & 63;
        Xs[i] = g_X2[((size_t)(b * 64 + c) * 32 + m) * 16 + q];
    }
    for (int i = tid; i < 4096; i += 256) {
        int c = i >> 6, d = i & 63;
        const float* p = wsrc + ((size_t)(d * 64 + c) * 256 + t_w * 16 + q) * 2;
        float wr = p[0], wi = p[1];
        ulonglong2 v; v.x = pack2(wr, wi); v.y = pack2(-wi, wr);
        Wpk[c * 64 + d] = v;
    }
    __syncthreads();

    const int b = tid >> 4;
    const int dl = tid & 15;
    u64 accA[4], accB[4];
    #pragma unroll
    for (int j = 0; j < 4; j++) { accA[j] = 0ull; accB[j] = 0ull; }

    #pragma unroll 4
    for (int c = 0; c < 64; c++) {
        float2 xv = Xs[b * 64 + c];
        u64 xr = pack2(xv.x, xv.x), xi = pack2(xv.y, xv.y);
        #pragma unroll
        for (int j = 0; j < 4; j++) {
            ulonglong2 wv = Wpk[c * 64 + dl + 16 * j];
            accA[j] = fma2(xr, wv.x, accA[j]);
            accB[j] = fma2(xi, wv.y, accB[j]);
        }
    }
    #pragma unroll
    for (int j = 0; j < 4; j++) {
        int d = dl + 16 * j;
        float2 ra = unpack2(accA[j]), rb = unpack2(accB[j]);
        g_Y[((size_t)(b * 64 + d) * 32 + m) * 16 + q] =
            make_float2(ra.x + rb.x, ra.y + rb.y);
    }
}

// ================= Inverse: parity-shared G build + 2-col symmetric w-GEMM ======
__global__ __launch_bounds__(256) void kCD(float* __restrict__ out) {
    __shared__ u64        twcs[256];     // (c, s)
    __shared__ ulonglong2 tw2[256];      // ((c,c),(s,s))
    __shared__ float2     Ys[512];       // [m][q]
    __shared__ ulonglong2 PQ[17 * 16];   // [mp][q]: (P, Qv)
    __shared__ float2     Gp[16 * 258];  // [q][h] = (a*Gre, -a*Gim)
    const int tid = threadIdx.x;
    const size_t bd = blockIdx.x;

    {
        float s, c;
        sincospif((float)tid * (1.0f / 128.0f), &s, &c);
        twcs[tid] = pack2(c, s);
        ulonglong2 t; t.x = pack2(c, c); t.y = pack2(s, s);
        tw2[tid] = t;
    }
    ((float4*)Ys)[tid] = ((const float4*)(g_Y + bd * 512))[tid];
    __syncthreads();

    {
        int mp = tid >> 4, q = tid & 15;     // mp = 0..15
        float2 Pv, Qv;
        if (mp == 0) { Pv = Ys[q]; Qv = make_float2(0.0f, 0.0f); }
        else {
            float2 ym = Ys[mp * 16 + q], yn = Ys[(32 - mp) * 16 + q];
            Pv = make_float2(ym.x + yn.x, ym.y + yn.y);
            Qv = make_float2(-(ym.y - yn.y), ym.x - yn.x);   // i*(Ym - Y-m)
        }
        ulonglong2 pq; pq.x = pack2(Pv.x, Pv.y); pq.y = pack2(Qv.x, Qv.y);
        PQ[mp * 16 + q] = pq;
    }
    if (tid < 16) {
        int q = tid;                         // mp = 16 (t = -16): Qv = -i*Y
        float2 y = Ys[16 * 16 + q];
        ulonglong2 pq; pq.x = pack2(y.x, y.y); pq.y = pack2(y.y, -y.x);
        PQ[16 * 16 + q] = pq;
    }
    __syncthreads();

    // Part 1: rows h0 and h0+128 share twiddles via parity of mp
    const u64 NEG1 = pack2(-1.0f, -1.0f);
    #pragma unroll 2
    for (int it = 0; it < 8; it++) {
        int task = tid + it * 256;           // 2048 = 128 h0 x 16 q
        int q = task & 15, h0 = task >> 4;
        u64 Se = 0ull, So = 0ull;
        #pragma unroll
        for (int mp = 0; mp <= 16; mp++) {
            ulonglong2 t  = tw2[(mp * h0) & 255];
            ulonglong2 pq = PQ[mp * 16 + q];
            if (mp & 1) { So = fma2(pq.x, t.x, So); So = fma2(pq.y, t.y, So); }
            else        { Se = fma2(pq.x, t.x, Se); Se = fma2(pq.y, t.y, Se); }
        }
        float a = (q == 0) ? (1.0f / 256.0f) : (2.0f / 256.0f);
        float2 v0 = unpack2(add2(Se, So));
        float2 v1 = unpack2(fma2(So, NEG1, Se));
        Gp[q * 258 + h0]       = make_float2(a * v0.x, -a * v0.y);
        Gp[q * 258 + h0 + 128] = make_float2(a * v1.x, -a * v1.y);
    }
    __syncthreads();

    // Part 2: 2 w' columns per thread, 4 h-groups
    const int wa = tid & 63;
    const int wb = wa + 64;
    const int hg = tid >> 6;
    u64 twa[16], twb[16];
    #pragma unroll
    for (int q = 0; q < 16; q++) {
        twa[q] = twcs[(q * wa) & 255];
        twb[q] = twcs[(q * wb) & 255];
    }

    float* ob = out + bd * 65536;
    const int hbase = hg * 64;
    #pragma unroll 2
    for (int hh = hbase; hh < hbase + 64; hh += 2) {
        u64 ca0 = 0ull, ca1 = 0ull, cb0 = 0ull, cb1 = 0ull;
        #pragma unroll
        for (int q = 0; q < 16; q++) {
            ulonglong2 g = *(const ulonglong2*)&Gp[q * 258 + hh];  // broadcast
            ca0 = fma2(g.x, twa[q], ca0);
            ca1 = fma2(g.y, twa[q], ca1);
            cb0 = fma2(g.x, twb[q], cb0);
            cb1 = fma2(g.y, twb[q], cb1);
        }
        float2 ra0 = unpack2(ca0), ra1 = unpack2(ca1);
        float2 rb0 = unpack2(cb0), rb1 = unpack2(cb1);
        ob[hh * 256 + wa]             = ra0.x + ra0.y;
        ob[(hh + 1) * 256 + wa]       = ra1.x + ra1.y;
        ob[hh * 256 + wb]             = rb0.x + rb0.y;
        ob[(hh + 1) * 256 + wb]       = rb1.x + rb1.y;
        ob[hh * 256 + 256 - wb]       = rb0.x - rb0.y;
        ob[(hh + 1) * 256 + 256 - wb] = rb1.x - rb1.y;
        if (wa) {
            ob[hh * 256 + 256 - wa]       = ra0.x - ra0.y;
            ob[(hh + 1) * 256 + 256 - wa] = ra1.x - ra1.y;
        }
    }
    // w = 128 column: cos(pi q) = (-1)^q, sin = 0
    {
        int h = tid;
        float acc = 0.0f;
        #pragma unroll
        for (int q = 0; q < 16; q++) {
            float v = Gp[q * 258 + h].x;
            acc += (q & 1) ? -v : v;
        }
        ob[h * 256 + 128] = acc;
    }
}

extern "C" void kernel_launch(void* const* d_in, const int* in_sizes, int n_in,
                              void* d_out, int out_size) {
    const float* x  = (const float*)d_in[0];
    const float* w1 = (const float*)d_in[1];
    const float* w2 = (const float*)d_in[2];
    float* out = (float*)d_out;

    const int SMEM_AB = 67984;
    const int SMEM_M  = 1024 * 8 + 4096 * 16;          // 73728
    cudaFuncSetAttribute(kAB, cudaFuncAttributeMaxDynamicSharedMemorySize, SMEM_AB);
    cudaFuncSetAttribute(kM,  cudaFuncAttributeMaxDynamicSharedMemorySize, SMEM_M);

    kAB<<<NBC, 256, SMEM_AB>>>(x);
    kM<<<512, 256, SMEM_M>>>(w1, w2);
    kCD<<<NBC, 256>>>(out);
}

// round 17
// speedup vs baseline: 1.1665x; 1.1665x over previous
#include <cuda_runtime.h>

// SpectralConv2d: B=16, C_IN=C_OUT=64, H=W=256, M=16
//  kAB (R14 proven): quartet-symmetry h-first DFT, cp.async triple-buffered,
//       phase-aliased smem -> 3 CTAs/SM.
//  kM : per-(m,q) complex channel mix [16x64]*[64x64].
//  kCD: parity-shared G build + w-PARITY-QUARTET inverse GEMM
//       (4 output cols per thread from one even/odd accumulation pair).

#define NBC   (16*64)       // 1024

typedef unsigned long long u64;

__device__ float2 g_X2[NBC * 32 * 16];     // [bc][m][q]
__device__ float2 g_Y [NBC * 32 * 16];     // [bd][m][q]

__device__ __forceinline__ u64 pack2(float lo, float hi) {
    u64 r; asm("mov.b64 %0, {%1,%2};" : "=l"(r) : "f"(lo), "f"(hi)); return r;
}
__device__ __forceinline__ float2 unpack2(u64 v) {
    float lo, hi; asm("mov.b64 {%0,%1}, %2;" : "=f"(lo), "=f"(hi) : "l"(v));
    return make_float2(lo, hi);
}
__device__ __forceinline__ u64 fma2(u64 a, u64 b, u64 c) {
    u64 d; asm("fma.rn.f32x2 %0, %1, %2, %3;" : "=l"(d) : "l"(a), "l"(b), "l"(c)); return d;
}
__device__ __forceinline__ u64 add2(u64 a, u64 b) {
    u64 d; asm("add.rn.f32x2 %0, %1, %2;" : "=l"(d) : "l"(a), "l"(b)); return d;
}
__device__ __forceinline__ void cp_async16(unsigned smem_addr, const void* gptr) {
    asm volatile("cp.async.cg.shared.global [%0], [%1], 16;"
                 :: "r"(smem_addr), "l"(gptr));
}
__device__ __forceinline__ void cp_commit() {
    asm volatile("cp.async.commit_group;");
}
template <int N>
__device__ __forceinline__ void cp_wait() {
    asm volatile("cp.async.wait_group %0;" :: "n"(N));
}

// ================= Fused stage A+B (quartet symmetry, phase-aliased smem) ======
// phase 1: twE ulonglong2[65*4]@0 | twO @4160 | tw16 u64[65]@8320 (pad 8848)
//          xbuf float[3][16][256] @8848 (49152)
// phase 2: P u64[17*257] @0 (pad 34960) | E2 ulonglong2[129*16] @34960 (33024)
// smem = 67984 -> 3 CTAs/SM
__global__ __launch_bounds__(256, 3) void kAB(const float* __restrict__ x) {
    extern __shared__ char sm[];
    ulonglong2* twE  = (ulonglong2*)sm;
    ulonglong2* twO  = (ulonglong2*)(sm + 4160);
    u64*        tw16 = (u64*)(sm + 8320);
    float*      xbuf = (float*)(sm + 8848);
    u64*        P    = (u64*)sm;                   // phase-2 alias
    ulonglong2* E2   = (ulonglong2*)(sm + 34960);  // phase-2 alias

    const int tid = threadIdx.x;
    const size_t bc = blockIdx.x;
    const float k = 1.0f / 256.0f;
    const float* xb_ = x + bc * 65536;
    const unsigned xbuf_base = (unsigned)__cvta_generic_to_shared(xbuf);

    const int i0 = tid >> 6, col = tid & 63;
    const float* gA = xb_ + (1 + i0) * 256 + col * 4;
    const float* gB = xb_ + (255 - i0) * 256 + col * 4;
    const float* gC = xb_ + (127 - i0) * 256 + col * 4;
    const float* gD = xb_ + (129 + i0) * 256 + col * 4;
    const unsigned sA = (unsigned)(i0 * 1024 + col * 16);

    auto issue = [&](int c) {
        const unsigned db = xbuf_base + (unsigned)((c % 3) * 16384);
        const int off = 1024 * c;
        cp_async16(db + sA,         gA + off);
        cp_async16(db + sA + 4096,  gB - off);
        cp_async16(db + sA + 8192,  gC - off);
        cp_async16(db + sA + 12288, gD + off);
        cp_commit();
    };

    issue(0);
    issue(1);

    if (tid < 64) {
        int h = tid + 1;
        float sc = (h == 64) ? (0.5f * k) : k;
        float cb[17], sb[17];
        #pragma unroll
        for (int m = 0; m < 17; m++) {
            float s, c;
            sincospif((float)((m * h) & 255) * (1.0f / 128.0f), &s, &c);
            cb[m] = c * sc; sb[m] = s * sc;
        }
        #pragma unroll
        for (int j = 0; j < 4; j++) {
            ulonglong2 ve, vo;
            ve.x = pack2(cb[4 * j], cb[4 * j + 2]);
            ve.y = pack2(sb[4 * j], sb[4 * j + 2]);
            vo.x = pack2(cb[4 * j + 1], cb[4 * j + 3]);
            vo.y = pack2(sb[4 * j + 1], sb[4 * j + 3]);
            twE[h * 4 + j] = ve;
            twO[h * 4 + j] = vo;
        }
        tw16[h] = pack2(cb[16], sb[16]);
    }

    const int w = tid;
    float x0 = xb_[w], x128 = xb_[32768 + w];
    __syncthreads();

    u64 accEA[4], accEB[4], accOA[4], accOB[4], acc16;
    {
        float ve = (x0 + x128) * k, vo = (x0 - x128) * k;
        u64 pe = pack2(ve, ve), po = pack2(vo, vo);
        #pragma unroll
        for (int j = 0; j < 4; j++) {
            accEA[j] = pe; accEB[j] = 0ull;
            accOA[j] = po; accOB[j] = 0ull;
        }
        acc16 = pack2(ve, 0.0f);
    }

    #pragma unroll 1
    for (int c = 0; c < 16; c++) {
        if (c == 15) { cp_wait<0>(); } else { cp_wait<1>(); }
        __syncthreads();
        if (c <= 13) issue(c + 2);

        const float* buf = xbuf + (c % 3) * 4096;
        const int hb = 4 * c + 1;
        #pragma unroll
        for (int i = 0; i < 4; i++) {
            float xa = buf[i * 256 + w];
            float xv = buf[1024 + i * 256 + w];
            float xc = buf[2048 + i * 256 + w];
            float xd = buf[3072 + i * 256 + w];
            float s_ = xa + xv, d_ = xa - xv;
            float s2 = xc + xd, d2 = xc - xd;
            float se = s_ + s2, so = s_ - s2;
            float de = d_ - d2, dO = d_ + d2;
            u64 sse = pack2(se, se), sso = pack2(so, so);
            u64 dde = pack2(de, de), ddo = pack2(dO, dO);
            const int ht = hb + i;
            const ulonglong2* tE = &twE[ht * 4];
            const ulonglong2* tO = &twO[ht * 4];
            #pragma unroll
            for (int j = 0; j < 4; j++) {
                ulonglong2 e = tE[j];
                ulonglong2 o = tO[j];
                accEA[j] = fma2(sse, e.x, accEA[j]);
                accEB[j] = fma2(dde, e.y, accEB[j]);
                accOA[j] = fma2(sso, o.x, accOA[j]);
                accOB[j] = fma2(ddo, o.y, accOB[j]);
            }
            acc16 = fma2(pack2(se, de), tw16[ht], acc16);
        }
    }
    __syncthreads();

    #pragma unroll
    for (int j = 0; j < 4; j++) {
        float2 aE = unpack2(accEA[j]), bE = unpack2(accEB[j]);
        float2 aO = unpack2(accOA[j]), bO = unpack2(accOB[j]);
        P[(4 * j) * 257 + w]     = pack2(aE.x, bE.x);
        P[(4 * j + 2) * 257 + w] = pack2(aE.y, bE.y);
        P[(4 * j + 1) * 257 + w] = pack2(aO.x, bO.x);
        P[(4 * j + 3) * 257 + w] = pack2(aO.y, bO.y);
    }
    P[16 * 257 + w] = acc16;
    for (int idx = tid; idx < 129 * 16; idx += 256) {
        int wp = idx >> 4, q = idx & 15;
        float s, c;
        sincospif((float)(q * wp) * (1.0f / 128.0f), &s, &c);
        ulonglong2 v; v.x = pack2(c, c); v.y = pack2(s, s);
        E2[idx] = v;
    }
    __syncthreads();

    for (int task = tid; task < 272; task += 256) {
        const int mp = task >> 4, q = task & 15;
        const u64* Pm = P + mp * 257;
        const u64 NEG1 = pack2(-1.0f, -1.0f);

        float sq = (q & 1) ? -1.0f : 1.0f;
        u64 acc1 = fma2(Pm[128], pack2(sq, sq), Pm[0]);   // (Cc, Dc)
        u64 acc2 = 0ull;                                   // (Cs, Ds)

        #pragma unroll 2
        for (int wp = 1; wp <= 127; wp++) {
            u64 Pa = Pm[wp];
            u64 Pb = Pm[256 - wp];
            u64 S = add2(Pa, Pb);
            u64 D = fma2(Pb, NEG1, Pa);
            ulonglong2 e = E2[wp * 16 + q];
            acc1 = fma2(S, e.x, acc1);
            acc2 = fma2(D, e.y, acc2);
        }
        float2 r1 = unpack2(acc1);
        float2 r2 = unpack2(acc2);
        float2* dst = g_X2 + bc * 512;
        if (mp <= 15) dst[mp * 16 + q]        = make_float2(r1.x - r2.y, -(r2.x + r1.y));
        if (mp >= 1)  dst[(32 - mp) * 16 + q] = make_float2(r1.x + r2.y, r1.y - r2.x);
    }
}

// ================= Channel mixing (unchanged) =================
__global__ __launch_bounds__(256) void kM(const float* __restrict__ w1,
                                          const float* __restrict__ w2) {
    extern __shared__ char smM[];
    float2* Xs = (float2*)smM;                       // [b*64+c]
    ulonglong2* Wpk = (ulonglong2*)(smM + 1024 * 8); // [c*64+d] = ((wr,wi),(-wi,wr))
    const int tid = threadIdx.x;
    const int m = blockIdx.x >> 4;
    const int q = blockIdx.x & 15;
    const float* wsrc = (m < 16) ? w1 : w2;
    const int t_w = (m < 16) ? m : (m - 16);

    for (int i = tid; i < 1024; i += 256) {
        int b = i >> 6, c = i & 63;
        Xs[i] = g_X2[((size_t)(b * 64 + c) * 32 + m) * 16 + q];
    }
    for (int i = tid; i < 4096; i += 256) {
        int c = i >> 6, d = i & 63;
        const float* p = wsrc + ((size_t)(d * 64 + c) * 256 + t_w * 16 + q) * 2;
        float wr = p[0], wi = p[1];
        ulonglong2 v; v.x = pack2(wr, wi); v.y = pack2(-wi, wr);
        Wpk[c * 64 + d] = v;
    }
    __syncthreads();

    const int b = tid >> 4;
    const int dl = tid & 15;
    u64 accA[4], accB[4];
    #pragma unroll
    for (int j = 0; j < 4; j++) { accA[j] = 0ull; accB[j] = 0ull; }

    #pragma unroll 4
    for (int c = 0; c < 64; c++) {
        float2 xv = Xs[b * 64 + c];
        u64 xr = pack2(xv.x, xv.x), xi = pack2(xv.y, xv.y);
        #pragma unroll
        for (int j = 0; j < 4; j++) {
            ulonglong2 wv = Wpk[c * 64 + dl + 16 * j];
            accA[j] = fma2(xr, wv.x, accA[j]);
            accB[j] = fma2(xi, wv.y, accB[j]);
        }
    }
    #pragma unroll
    for (int j = 0; j < 4; j++) {
        int d = dl + 16 * j;
        float2 ra = unpack2(accA[j]), rb = unpack2(accB[j]);
        g_Y[((size_t)(b * 64 + d) * 32 + m) * 16 + q] =
            make_float2(ra.x + rb.x, ra.y + rb.y);
    }
}

// ================= Inverse: parity G build + w-parity-quartet GEMM =============
__global__ __launch_bounds__(256) void kCD(float* __restrict__ out) {
    __shared__ u64        twcs[256];     // (c, s)
    __shared__ ulonglong2 tw2[256];      // ((c,c),(s,s))
    __shared__ float2     Ys[512];       // [m][q]
    __shared__ ulonglong2 PQ[17 * 16];   // [mp][q]: (P, Qv)
    __shared__ float2     Gp[16 * 258];  // [q][h] = (a*Gre, -a*Gim)
    const int tid = threadIdx.x;
    const size_t bd = blockIdx.x;

    {
        float s, c;
        sincospif((float)tid * (1.0f / 128.0f), &s, &c);
        twcs[tid] = pack2(c, s);
        ulonglong2 t; t.x = pack2(c, c); t.y = pack2(s, s);
        tw2[tid] = t;
    }
    ((float4*)Ys)[tid] = ((const float4*)(g_Y + bd * 512))[tid];
    __syncthreads();

    {
        int mp = tid >> 4, q = tid & 15;     // mp = 0..15
        float2 Pv, Qv;
        if (mp == 0) { Pv = Ys[q]; Qv = make_float2(0.0f, 0.0f); }
        else {
            float2 ym = Ys[mp * 16 + q], yn = Ys[(32 - mp) * 16 + q];
            Pv = make_float2(ym.x + yn.x, ym.y + yn.y);
            Qv = make_float2(-(ym.y - yn.y), ym.x - yn.x);   // i*(Ym - Y-m)
        }
        ulonglong2 pq; pq.x = pack2(Pv.x, Pv.y); pq.y = pack2(Qv.x, Qv.y);
        PQ[mp * 16 + q] = pq;
    }
    if (tid < 16) {
        int q = tid;                         // mp = 16 (t = -16): Qv = -i*Y
        float2 y = Ys[16 * 16 + q];
        ulonglong2 pq; pq.x = pack2(y.x, y.y); pq.y = pack2(y.y, -y.x);
        PQ[16 * 16 + q] = pq;
    }
    __syncthreads();

    // Part 1: rows h0 and h0+128 share twiddles via parity of mp
    const u64 NEG1 = pack2(-1.0f, -1.0f);
    #pragma unroll 2
    for (int it = 0; it < 8; it++) {
        int task = tid + it * 256;           // 2048 = 128 h0 x 16 q
        int q = task & 15, h0 = task >> 4;
        u64 Se = 0ull, So = 0ull;
        #pragma unroll
        for (int mp = 0; mp <= 16; mp++) {
            ulonglong2 t  = tw2[(mp * h0) & 255];
            ulonglong2 pq = PQ[mp * 16 + q];
            if (mp & 1) { So = fma2(pq.x, t.x, So); So = fma2(pq.y, t.y, So); }
            else        { Se = fma2(pq.x, t.x, Se); Se = fma2(pq.y, t.y, Se); }
        }
        float a = (q == 0) ? (1.0f / 256.0f) : (2.0f / 256.0f);
        float2 v0 = unpack2(add2(Se, So));
        float2 v1 = unpack2(fma2(So, NEG1, Se));
        Gp[q * 258 + h0]       = make_float2(a * v0.x, -a * v0.y);
        Gp[q * 258 + h0 + 128] = make_float2(a * v1.x, -a * v1.y);
    }
    __syncthreads();

    // Part 2: w-parity quartet — thread (wa, h-group); even/odd-q accumulators
    // produce cols {wa, 256-wa, wa+128, 128-wa} from one twiddle set.
    const int wa = tid & 63;
    const int hg = tid >> 6;
    u64 twa[16];
    #pragma unroll
    for (int q = 0; q < 16; q++) twa[q] = twcs[(q * wa) & 255];   // (cos, sin)

    float* ob = out + bd * 65536;
    const int hbase = hg * 64;
    #pragma unroll 2
    for (int hh = hbase; hh < hbase + 64; hh += 2) {
        u64 ce0 = 0ull, co0 = 0ull, ce1 = 0ull, co1 = 0ull;
        #pragma unroll
        for (int q = 0; q < 16; q++) {
            ulonglong2 g = *(const ulonglong2*)&Gp[q * 258 + hh];  // broadcast
            if (q & 1) {
                co0 = fma2(g.x, twa[q], co0);
                co1 = fma2(g.y, twa[q], co1);
            } else {
                ce0 = fma2(g.x, twa[q], ce0);
                ce1 = fma2(g.y, twa[q], ce1);
            }
        }
        float2 e0 = unpack2(add2(ce0, co0));
        float2 d0 = unpack2(fma2(co0, NEG1, ce0));
        float2 e1 = unpack2(add2(ce1, co1));
        float2 d1 = unpack2(fma2(co1, NEG1, ce1));
        float* r0 = ob + hh * 256;
        float* r1 = r0 + 256;
        r0[wa]        = e0.x + e0.y;
        r1[wa]        = e1.x + e1.y;
        r0[wa + 128]  = d0.x + d0.y;
        r1[wa + 128]  = d1.x + d1.y;
        if (wa) {
            r0[256 - wa] = e0.x - e0.y;
            r1[256 - wa] = e1.x - e1.y;
            r0[128 - wa] = d0.x - d0.y;
            r1[128 - wa] = d1.x - d1.y;
        }
    }
    // w = 64 / 192 columns: cos(q pi/2), sin(q pi/2) in {0, +-1}
    {
        int h = tid;
        float cC = 0.0f, sS = 0.0f;
        #pragma unroll
        for (int q = 0; q < 16; q += 2) {        // even q: cos = (-1)^(q/2)
            float v = Gp[q * 258 + h].x;
            cC += ((q >> 1) & 1) ? -v : v;
        }
        #pragma unroll
        for (int q = 1; q < 16; q += 2) {        // odd q: sin = (-1)^((q-1)/2)
            float v = Gp[q * 258 + h].y;
            sS += (((q - 1) >> 1) & 1) ? -v : v;
        }
        ob[h * 256 + 64]  = cC + sS;
        ob[h * 256 + 192] = cC - sS;
    }
}

extern "C" void kernel_launch(void* const* d_in, const int* in_sizes, int n_in,
                              void* d_out, int out_size) {
    const float* x  = (const float*)d_in[0];
    const float* w1 = (const float*)d_in[1];
    const float* w2 = (const float*)d_in[2];
    float* out = (float*)d_out;

    const int SMEM_AB = 67984;
    const int SMEM_M  = 1024 * 8 + 4096 * 16;          // 73728
    cudaFuncSetAttribute(kAB, cudaFuncAttributeMaxDynamicSharedMemorySize, SMEM_AB);
    cudaFuncSetAttribute(kM,  cudaFuncAttributeMaxDynamicSharedMemorySize, SMEM_M);

    kAB<<<NBC, 256, SMEM_AB>>>(x);
    kM<<<512, 256, SMEM_M>>>(w1, w2);
    kCD<<<NBC, 256>>>(out);
}